// round 14
// baseline (speedup 1.0000x reference)
#include <cuda_runtime.h>
#include <math.h>

#define BSZ  1024
#define SLEN 512
#define TT   64
#define HALF 256   // sequence split point: fwd does steps 1..255, bwd does 256..511
#define KRN  6     // renormalize every KRN unmasked steps (exact pow-2, numerics-invariant)

__device__ double g_res[BSZ];
__device__ int    g_cnt[BSZ];
__device__ int    g_ticket;    // zero-init; last block resets to 0 (replay-safe)

static __device__ __forceinline__ unsigned long long pk2(float x, float y) {
    unsigned long long r;
    asm("mov.b64 %0, {%1, %2};" : "=l"(r) : "f"(x), "f"(y));
    return r;
}
static __device__ __forceinline__ float2 upk2(unsigned long long v) {
    float2 r;
    asm("mov.b64 {%0, %1}, %2;" : "=f"(r.x), "=f"(r.y) : "l"(v));
    return r;
}
static __device__ __forceinline__ unsigned long long ffma2(unsigned long long a,
                                                           unsigned long long b,
                                                           unsigned long long c) {
    unsigned long long d;
    asm("fma.rn.f32x2 %0, %1, %2, %3;" : "=l"(d) : "l"(a), "l"(b), "l"(c));
    return d;
}
static __device__ __forceinline__ unsigned long long fadd2(unsigned long long a,
                                                           unsigned long long b) {
    unsigned long long d;
    asm("add.rn.f32x2 %0, %1, %2;" : "=l"(d) : "l"(a), "l"(b));
    return d;
}

// One block = one chain. Warp 0: forward alpha. Warp 1: backward gamma.
__global__ __launch_bounds__(64, 4)
void crf_forward(const float* __restrict__ e, const int* __restrict__ tags,
                 const unsigned char* __restrict__ mask,
                 const float* __restrict__ st, const float* __restrict__ et,
                 const float* __restrict__ tmat, float* __restrict__ out)
{
    __shared__ __align__(16) float pbuf[2][TT];          // forward p, double buffered
    __shared__ __align__(16) float ubuf[2][TT];          // backward u, double buffered
    __shared__ unsigned long long gbuf[32];              // gamma handoff (packed)
    __shared__ float s_scB, s_pendG;
    __shared__ int   s_cnB, s_EaccG;
    __shared__ int   s_t;

    const int w     = threadIdx.x >> 5;
    const int lane  = threadIdx.x & 31;
    const int chain = blockIdx.x;
    const int c0 = 2 * lane, c1 = c0 + 1;   // this lane's two (adjacent) states

    const float*         eb = e    + (size_t)chain * (SLEN * TT);
    const int*           tb = tags + chain * SLEN;
    const unsigned char* mb = mask + chain * SLEN;

    // forward-side results (live across the __syncthreads)
    float p0 = 0.f, p1 = 0.f, pend = 1.0f, base = 0.f, scp = 0.f;
    int   Eacc = 0, cntp = 0;

    if (w == 0) {
        // ================= FORWARD: alpha over steps 1..HALF-1 =================
        // column tables: Ea[m]=(E[2m][c0],E[2m+1][c0]), Eb[m]=(E[2m][c1],E[2m+1][c1])
        unsigned long long Ea[32], Eb[32];
#pragma unroll
        for (int m = 0; m < 32; ++m) {
            const float2 t0v = *reinterpret_cast<const float2*>(&tmat[(2 * m)     * TT + c0]);
            const float2 t1v = *reinterpret_cast<const float2*>(&tmat[(2 * m + 1) * TT + c0]);
            Ea[m] = pk2(__expf(t0v.x), __expf(t1v.x));
            Eb[m] = pk2(__expf(t0v.y), __expf(t1v.y));
        }
        // mask words (uniform regs) + score/count over first half
        unsigned mwF[9];
#pragma unroll
        for (int k2 = 0; k2 < 8; ++k2) {
            int s = k2 * 32 + lane;
            int m = mb[s];
            mwF[k2] = __ballot_sync(0xffffffffu, m != 0);
            cntp += m;
            if (s > 0 && m) {
                int tp = tb[s - 1], tn = tb[s];
                scp += __ldg(&tmat[tp * TT + tn]) + eb[s * TT + tn];
            }
        }
        mwF[8] = 0u;
#pragma unroll
        for (int off = 16; off; off >>= 1) {
            scp  += __shfl_xor_sync(0xffffffffu, scp, off);
            cntp += __shfl_xor_sync(0xffffffffu, cntp, off);
        }
        // init alpha_0
        float2 ev0 = *reinterpret_cast<const float2*>(eb + c0);
        float n0 = st[c0] + ev0.x;
        float n1 = st[c1] + ev0.y;
        base = fmaxf(n0, n1);
#pragma unroll
        for (int off = 16; off; off >>= 1)
            base = fmaxf(base, __shfl_xor_sync(0xffffffffu, base, off));
        p0 = __expf(n0 - base);
        p1 = __expf(n1 - base);
        *reinterpret_cast<unsigned long long*>(&pbuf[0][c0]) = pk2(p0, p1);
        int cur = 0, rc = 0;
        __syncwarp();

        auto do_fstep = [&](float2 ec, unsigned mk) {
            if (!mk) return;
            float F0 = __expf(ec.x) * pend;
            float F1 = __expf(ec.y) * pend;
            pend = 1.0f;
            const ulonglong2* rp = reinterpret_cast<const ulonglong2*>(pbuf[cur]);
            unsigned long long x0 = 0ull, x1 = 0ull, x2 = 0ull, x3 = 0ull;
            unsigned long long y0 = 0ull, y1 = 0ull, y2 = 0ull, y3 = 0ull;
#pragma unroll
            for (int k = 0; k < 4; ++k) {
                ulonglong2 v0 = rp[4 * k];
                ulonglong2 v1 = rp[4 * k + 1];
                ulonglong2 v2 = rp[4 * k + 2];
                ulonglong2 v3 = rp[4 * k + 3];
                x0 = ffma2(v0.x, Ea[8 * k],     x0);  y0 = ffma2(v0.x, Eb[8 * k],     y0);
                x1 = ffma2(v0.y, Ea[8 * k + 1], x1);  y1 = ffma2(v0.y, Eb[8 * k + 1], y1);
                x2 = ffma2(v1.x, Ea[8 * k + 2], x2);  y2 = ffma2(v1.x, Eb[8 * k + 2], y2);
                x3 = ffma2(v1.y, Ea[8 * k + 3], x3);  y3 = ffma2(v1.y, Eb[8 * k + 3], y3);
                x0 = ffma2(v2.x, Ea[8 * k + 4], x0);  y0 = ffma2(v2.x, Eb[8 * k + 4], y0);
                x1 = ffma2(v2.y, Ea[8 * k + 5], x1);  y1 = ffma2(v2.y, Eb[8 * k + 5], y1);
                x2 = ffma2(v3.x, Ea[8 * k + 6], x2);  y2 = ffma2(v3.x, Eb[8 * k + 6], y2);
                x3 = ffma2(v3.y, Ea[8 * k + 7], x3);  y3 = ffma2(v3.y, Eb[8 * k + 7], y3);
            }
            float2 qa = upk2(fadd2(fadd2(x0, x1), fadd2(x2, x3)));
            float2 qb = upk2(fadd2(fadd2(y0, y1), fadd2(y2, y3)));
            float q0 = (qa.x + qa.y) * F0;
            float q1 = (qb.x + qb.y) * F1;
            p0 = q0; p1 = q1;
            if (++rc >= KRN) {      // measure now, apply via pend next step (exact)
                rc = 0;
                unsigned mxu = __reduce_max_sync(0xffffffffu,
                                                 __float_as_uint(fmaxf(q0, q1)));
                int ke = (int)(mxu >> 23) - 127;
                Eacc += ke;
                pend = __int_as_float((127 - ke) << 23);
            }
            cur ^= 1;
            *reinterpret_cast<unsigned long long*>(&pbuf[cur][c0]) = pk2(q0, q1);
            __syncwarp();
        };

        float2 eA = *reinterpret_cast<const float2*>(eb + 1 * TT + c0);
        float2 eB = *reinterpret_cast<const float2*>(eb + 2 * TT + c0);
        float2 eC = *reinterpret_cast<const float2*>(eb + 3 * TT + c0);
        float2 eD = *reinterpret_cast<const float2*>(eb + 4 * TT + c0);
#pragma unroll 1
        for (int s = 1; s < HALF; s += 4) {
            float2 cA = eA, cB = eB, cC = eC, cD = eD;
            unsigned mb4 = __funnelshift_r(mwF[s >> 5], mwF[(s + 3) >> 5], s & 31);
            if (s + 4 < HALF) eA = *reinterpret_cast<const float2*>(eb + (s + 4) * TT + c0);
            if (s + 5 < HALF) eB = *reinterpret_cast<const float2*>(eb + (s + 5) * TT + c0);
            if (s + 6 < HALF) eC = *reinterpret_cast<const float2*>(eb + (s + 6) * TT + c0);
            if (s + 7 < HALF) eD = *reinterpret_cast<const float2*>(eb + (s + 7) * TT + c0);
            do_fstep(cA, mb4 & 1u);
            if (s + 1 < HALF) do_fstep(cB, mb4 & 2u);
            if (s + 2 < HALF) do_fstep(cC, mb4 & 4u);
            if (s + 3 < HALF) do_fstep(cD, mb4 & 8u);
        }
    } else {
        // ================= BACKWARD: gamma over steps SLEN-1..HALF =================
        // row tables: Ra[m]=(E[c0][2m],E[c0][2m+1]), Rb[m]=(E[c1][2m],E[c1][2m+1])
        unsigned long long Ra[32], Rb[32];
#pragma unroll
        for (int m = 0; m < 32; ++m) {
            const float2 r0 = *reinterpret_cast<const float2*>(&tmat[c0 * TT + 2 * m]);
            const float2 r1 = *reinterpret_cast<const float2*>(&tmat[c1 * TT + 2 * m]);
            Ra[m] = pk2(__expf(r0.x), __expf(r0.y));
            Rb[m] = pk2(__expf(r1.x), __expf(r1.y));
        }
        unsigned mwB[8];
        float scB = 0.f;
        int cnB = 0;
#pragma unroll
        for (int k2 = 0; k2 < 8; ++k2) {
            int s = (k2 + 8) * 32 + lane;
            int m = mb[s];
            mwB[k2] = __ballot_sync(0xffffffffu, m != 0);
            cnB += m;
            if (m) {
                int tp = tb[s - 1], tn = tb[s];
                scB += __ldg(&tmat[tp * TT + tn]) + eb[s * TT + tn];
            }
        }
#pragma unroll
        for (int off = 16; off; off >>= 1) {
            scB += __shfl_xor_sync(0xffffffffu, scB, off);
            cnB += __shfl_xor_sync(0xffffffffu, cnB, off);
        }
        // init gamma = exp(et)
        float g0 = __expf(et[c0]);
        float g1 = __expf(et[c1]);
        int cur = 0, EaccG = 0, rc = 0;
        float pendG = 1.0f;

        auto do_bstep = [&](float2 ec, unsigned mk) {
            if (!mk) return;
            float u0 = g0 * (__expf(ec.x) * pendG);
            float u1 = g1 * (__expf(ec.y) * pendG);
            pendG = 1.0f;
            cur ^= 1;
            *reinterpret_cast<unsigned long long*>(&ubuf[cur][c0]) = pk2(u0, u1);
            __syncwarp();
            const ulonglong2* rp = reinterpret_cast<const ulonglong2*>(ubuf[cur]);
            unsigned long long x0 = 0ull, x1 = 0ull, x2 = 0ull, x3 = 0ull;
            unsigned long long y0 = 0ull, y1 = 0ull, y2 = 0ull, y3 = 0ull;
#pragma unroll
            for (int k = 0; k < 4; ++k) {
                ulonglong2 v0 = rp[4 * k];
                ulonglong2 v1 = rp[4 * k + 1];
                ulonglong2 v2 = rp[4 * k + 2];
                ulonglong2 v3 = rp[4 * k + 3];
                x0 = ffma2(v0.x, Ra[8 * k],     x0);  y0 = ffma2(v0.x, Rb[8 * k],     y0);
                x1 = ffma2(v0.y, Ra[8 * k + 1], x1);  y1 = ffma2(v0.y, Rb[8 * k + 1], y1);
                x2 = ffma2(v1.x, Ra[8 * k + 2], x2);  y2 = ffma2(v1.x, Rb[8 * k + 2], y2);
                x3 = ffma2(v1.y, Ra[8 * k + 3], x3);  y3 = ffma2(v1.y, Rb[8 * k + 3], y3);
                x0 = ffma2(v2.x, Ra[8 * k + 4], x0);  y0 = ffma2(v2.x, Rb[8 * k + 4], y0);
                x1 = ffma2(v2.y, Ra[8 * k + 5], x1);  y1 = ffma2(v2.y, Rb[8 * k + 5], y1);
                x2 = ffma2(v3.x, Ra[8 * k + 6], x2);  y2 = ffma2(v3.x, Rb[8 * k + 6], y2);
                x3 = ffma2(v3.y, Ra[8 * k + 7], x3);  y3 = ffma2(v3.y, Rb[8 * k + 7], y3);
            }
            float2 ga = upk2(fadd2(fadd2(x0, x1), fadd2(x2, x3)));
            float2 gb = upk2(fadd2(fadd2(y0, y1), fadd2(y2, y3)));
            g0 = ga.x + ga.y;
            g1 = gb.x + gb.y;
            if (++rc >= KRN) {
                rc = 0;
                unsigned mxu = __reduce_max_sync(0xffffffffu,
                                                 __float_as_uint(fmaxf(g0, g1)));
                int ke = (int)(mxu >> 23) - 127;
                EaccG += ke;
                pendG = __int_as_float((127 - ke) << 23);
            }
        };

        // descending, groups aligned to 4 (sg covers steps sg..sg+3, processed high->low)
        float2 eA = *reinterpret_cast<const float2*>(eb + 511 * TT + c0);
        float2 eB = *reinterpret_cast<const float2*>(eb + 510 * TT + c0);
        float2 eC = *reinterpret_cast<const float2*>(eb + 509 * TT + c0);
        float2 eD = *reinterpret_cast<const float2*>(eb + 508 * TT + c0);
#pragma unroll 1
        for (int sg = SLEN - 4; sg >= HALF; sg -= 4) {
            float2 cA = eA, cB = eB, cC = eC, cD = eD;
            unsigned bits = (mwB[(sg >> 5) - 8] >> (sg & 31)) & 0xFu; // bit j = step sg+j
            if (sg - 4 >= HALF) {
                eA = *reinterpret_cast<const float2*>(eb + (sg - 1) * TT + c0);
                eB = *reinterpret_cast<const float2*>(eb + (sg - 2) * TT + c0);
                eC = *reinterpret_cast<const float2*>(eb + (sg - 3) * TT + c0);
                eD = *reinterpret_cast<const float2*>(eb + (sg - 4) * TT + c0);
            }
            do_bstep(cA, bits & 8u);   // step sg+3
            do_bstep(cB, bits & 4u);   // step sg+2
            do_bstep(cC, bits & 2u);   // step sg+1
            do_bstep(cD, bits & 1u);   // step sg
        }

        // handoff to warp 0
        gbuf[lane] = pk2(g0, g1);
        if (lane == 0) {
            s_scB   = scB;
            s_cnB   = cnB;
            s_pendG = pendG;
            s_EaccG = EaccG;
        }
    }
    __syncthreads();

    // ---- junction: Z = alpha · gamma (warp 0) ----
    if (w == 0) {
        float2 gg = upk2(gbuf[lane]);
        float z = p0 * gg.x + p1 * gg.y;
#pragma unroll
        for (int off = 16; off; off >>= 1)
            z += __shfl_xor_sync(0xffffffffu, z, off);
        if (lane == 0) {
            float zz = z * pend * s_pendG;
            double logZ = (double)base
                        + (double)(Eacc + s_EaccG) * 0.6931471805599453094
                        + log((double)zz);
            int   cnt   = cntp + s_cnB;
            int   t0    = tb[0];
            float score = scp + s_scB + st[t0] + eb[t0] + et[tb[cnt - 1]];
            g_res[chain] = (double)score - logZ;
            g_cnt[chain] = cnt;
        }
    }

    // ---- last-block fused finalization (deterministic order) ----
    __syncthreads();
    if (threadIdx.x == 0) {
        __threadfence();
        s_t = atomicAdd(&g_ticket, 1);
    }
    __syncthreads();
    if (s_t == (int)gridDim.x - 1) {
        const int tid = threadIdx.x;       // 64 threads
        double acc = 0.0;
        int    cnt = 0;
#pragma unroll
        for (int i = 0; i < BSZ / 64; ++i) {   // 16 chains per thread
            int idx = tid + i * 64;
            acc += g_res[idx];
            cnt += g_cnt[idx];
        }
#pragma unroll
        for (int off = 16; off; off >>= 1) {
            acc += __shfl_xor_sync(0xffffffffu, acc, off);
            cnt += __shfl_xor_sync(0xffffffffu, cnt, off);
        }
        __shared__ double sacc[2];
        __shared__ int    scnt[2];
        if (lane == 0) { sacc[w] = acc; scnt[w] = cnt; }
        __syncthreads();
        if (tid == 0) {
            double ta = sacc[0] + sacc[1];
            int    tc = scnt[0] + scnt[1];
            out[0] = (float)(ta / (double)tc);
            g_ticket = 0;                      // reset for next graph replay
        }
    }
}

extern "C" void kernel_launch(void* const* d_in, const int* in_sizes, int n_in,
                              void* d_out, int out_size)
{
    const float*         e    = (const float*)d_in[0];
    const int*           tags = (const int*)d_in[1];
    const unsigned char* mask = (const unsigned char*)d_in[2];
    const float*         st   = (const float*)d_in[3];
    const float*         et   = (const float*)d_in[4];
    const float*         t    = (const float*)d_in[5];

    crf_forward<<<BSZ, 64>>>(e, tags, mask, st, et, t, (float*)d_out);
}